// round 10
// baseline (speedup 1.0000x reference)
#include <cuda_runtime.h>
#include <cuda_bf16.h>
#include <float.h>
#include <stdint.h>

#define B        16
#define H        320
#define W        320
#define HW       (H * W)
#define P        64
#define K_TOP    100
#define NBIN     256         // bins over (0.5, 1.0) by float-bit mantissa
#define SEGCAP   512         // per-(batch,bin) segment capacity
#define KEYCAP   1024        // selector smem key cap (> K_TOP + SEGCAP)
#define LBUF     1024        // per-block candidate cap
#define TR       10          // rows per block (H % TR == 0)
#define NBLK     (H / TR)    // 32 blocks per batch

// Output layout (float32, tuple order): coors | params | scores | mask
#define OFF_COORS  0
#define OFF_PARAMS 3200
#define OFF_SCORES 105600
#define OFF_MASK   107200

// Device scratch (zero-init at module load; selector resets -> replay safe)
__device__ unsigned           g_binc[B * NBIN];
__device__ unsigned           g_done[B];
__device__ unsigned long long g_seg[(size_t)B * NBIN * SEGCAP];

static __device__ __forceinline__ float fmax3(float a, float b, float c) {
    return fmaxf(fmaxf(a, b), c);
}
// bin 0..255 over score bits in [0x3F000000, 0x3F800000)
static __device__ __forceinline__ unsigned binOf(unsigned bits) {
    unsigned bn = (bits - 0x3F000000u) >> 15;
    return bn > (NBIN - 1u) ? (NBIN - 1u) : bn;
}

union SmemU {
    struct {                                    // phase 1: NMS tile
        float tile[(TR + 2) * W];               // 15360 B
        float cmax[TR * W];                     // 12800 B
    } a;
    struct {                                    // phase 2: selection
        unsigned long long keys[KEYCAP];        // 8192 B
        float score[K_TOP];
        int   y[K_TOP];
        int   x[K_TOP];
        int   valid[K_TOP];
    } s;
};

// ---------------------------------------------------------------------------
// Fused kernel. Grid (NBLK, B), 256 threads.
// ---------------------------------------------------------------------------
__global__ __launch_bounds__(256) void k_fused(const float* __restrict__ hms,
                                               const float* __restrict__ pms,
                                               float* __restrict__ out) {
    __shared__ SmemU u;
    __shared__ unsigned long long s_buf[LBUF];
    __shared__ unsigned s_hist[NBIN];    // phase1: local hist | phase2: global counts
    __shared__ unsigned s_gbase[NBIN];   // phase1: seg bases  | phase2: incl. prefix
    __shared__ unsigned s_loc[NBIN];     // phase1: cursors
    __shared__ unsigned s_wsum[8];
    __shared__ unsigned s_cnt, s_ticket;
    __shared__ int s_c;

    const int b    = blockIdx.y;
    const int y0   = blockIdx.x * TR;
    const int tid  = threadIdx.x;
    const int lane = tid & 31;
    const int wid  = tid >> 5;
    const float* hb = hms + b * HW;

    if (tid == 0) s_cnt = 0;
    s_hist[tid] = 0u;                    // NBIN == blockDim

    // ======================= Phase 1: tiled 3x3 NMS ========================
    #pragma unroll
    for (int uu = 0; uu < 4; uu++) {
        int i = tid + uu * 256;
        if (i < (TR + 2) * (W / 4)) {
            int r  = i / (W / 4);
            int gy = y0 - 1 + r;
            float4 v = make_float4(-FLT_MAX, -FLT_MAX, -FLT_MAX, -FLT_MAX);
            if (gy >= 0 && gy < H)
                v = ((const float4*)(hb + gy * W))[i - r * (W / 4)];
            ((float4*)u.a.tile)[i] = v;
        }
    }
    __syncthreads();

    // vertical 3-max
    #pragma unroll
    for (int uu = 0; uu < 4; uu++) {
        int i = tid + uu * 256;
        if (i < TR * (W / 4)) {
            int r  = i / (W / 4);
            int c4 = i - r * (W / 4);
            float4 a = ((const float4*)u.a.tile)[(r    ) * (W / 4) + c4];
            float4 m = ((const float4*)u.a.tile)[(r + 1) * (W / 4) + c4];
            float4 d = ((const float4*)u.a.tile)[(r + 2) * (W / 4) + c4];
            float4 o;
            o.x = fmax3(a.x, m.x, d.x);
            o.y = fmax3(a.y, m.y, d.y);
            o.z = fmax3(a.z, m.z, d.z);
            o.w = fmax3(a.w, m.w, d.w);
            ((float4*)u.a.cmax)[i] = o;
        }
    }
    __syncthreads();

    // horizontal 3-max + peak test + warp-aggregated compaction
    // (TR*W/4 = 800 = 25 warps: the guard is warp-uniform, ballots are safe)
    #pragma unroll
    for (int uu = 0; uu < 4; uu++) {
        int i = tid + uu * 256;
        if (i < TR * (W / 4)) {
            int r  = i / (W / 4);
            int c4 = i - r * (W / 4);
            int x0 = c4 * 4;
            float4 mid = ((const float4*)u.a.tile)[(r + 1) * (W / 4) + c4];
            float4 cm  = ((const float4*)u.a.cmax)[r * (W / 4) + c4];
            float lf = (c4 > 0)         ? u.a.cmax[r * W + x0 - 1] : cm.x;
            float rt = (c4 < W / 4 - 1) ? u.a.cmax[r * W + x0 + 4] : cm.w;

            float wm[4];
            wm[0] = fmax3(lf,   cm.x, cm.y);
            wm[1] = fmax3(cm.x, cm.y, cm.z);
            wm[2] = fmax3(cm.y, cm.z, cm.w);
            wm[3] = fmax3(cm.z, cm.w, rt);
            float mv[4] = {mid.x, mid.y, mid.z, mid.w};

            #pragma unroll
            for (int e = 0; e < 4; e++) {
                bool cand = (mv[e] > 0.5f) && (mv[e] >= wm[e]);
                unsigned bal = __ballot_sync(0xffffffffu, cand);
                if (bal) {
                    unsigned base = 0;
                    if (lane == 0) base = atomicAdd(&s_cnt, (unsigned)__popc(bal));
                    base = __shfl_sync(0xffffffffu, base, 0);
                    if (cand) {
                        unsigned pos = base + (unsigned)__popc(bal & ((1u << lane) - 1u));
                        if (pos < LBUF) {
                            unsigned bits = __float_as_uint(mv[e]);
                            atomicAdd(&s_hist[binOf(bits)], 1u);
                            unsigned pixIdx = (unsigned)((y0 + r) * W + x0 + e);
                            s_buf[pos] = ((unsigned long long)bits << 32)
                                       | (unsigned)(~pixIdx);
                        }
                    }
                }
            }
        }
    }
    __syncthreads();

    // reserve per-bin global ranges
    {
        unsigned h = s_hist[tid];
        s_gbase[tid] = h ? atomicAdd(&g_binc[b * NBIN + tid], h) : 0u;
        s_loc[tid] = 0u;
    }
    __syncthreads();

    // scatter keys into bin segments
    unsigned nb = s_cnt;
    if (nb > LBUF) nb = LBUF;
    for (unsigned i = tid; i < nb; i += 256) {
        unsigned long long key = s_buf[i];
        unsigned bin  = binOf((unsigned)(key >> 32));
        unsigned slot = s_gbase[bin] + atomicAdd(&s_loc[bin], 1u);
        if (slot < SEGCAP)
            g_seg[(size_t)(b * NBIN + bin) * SEGCAP + slot] = key;
    }

    // ================= Ticket: last block becomes selector ==================
    __threadfence();
    __syncthreads();
    if (tid == 0) s_ticket = atomicAdd(&g_done[b], 1u);
    __syncthreads();
    if (s_ticket != NBLK - 1) return;
    if (tid == 0) g_done[b] = 0u;        // reset for next replay

    // ======================= Phase 2: selection ============================
    unsigned h;
    {
        unsigned v = atomicExch(&g_binc[b * NBIN + tid], 0u);  // read + reset
        h = v > SEGCAP ? (unsigned)SEGCAP : v;
        s_hist[tid] = h;
    }
    if (tid < K_TOP) { u.s.valid[tid] = 0; u.s.y[tid] = 0; u.s.x[tid] = 0; u.s.score[tid] = 0.f; }
    if (tid == 0) s_c = 0;
    __syncthreads();

    // inclusive prefix scan over 256 bins (warp shuffles + 8-wide combine)
    unsigned x = h;
    #pragma unroll
    for (int d = 1; d < 32; d <<= 1) {
        unsigned t = __shfl_up_sync(0xffffffffu, x, d);
        if (lane >= d) x += t;
    }
    if (lane == 31) s_wsum[wid] = x;
    __syncthreads();
    if (tid < 8) {
        unsigned y = s_wsum[tid];
        #pragma unroll
        for (int d = 1; d < 8; d <<= 1) {
            unsigned t = __shfl_up_sync(0xffu, y, d);
            if (tid >= d) y += t;
        }
        s_wsum[tid] = y;
    }
    __syncthreads();
    unsigned Pinc = x + (wid ? s_wsum[wid - 1] : 0u);
    s_gbase[tid] = Pinc;
    __syncthreads();

    const unsigned T = s_gbase[NBIN - 1];
    if (T - Pinc + h >= K_TOP) atomicMax(&s_c, tid);  // suffix-inclusive >= K
    __syncthreads();
    const int c = s_c;
    const unsigned Pc = s_gbase[c] - s_hist[c];        // keys in bins < c
    unsigned n = T - Pc;
    if (n > KEYCAP) n = KEYCAP;
    __syncthreads();

    // load only keys from bins >= c (binary search over inclusive prefix)
    for (unsigned i = tid; i < n; i += 256) {
        unsigned g = i + Pc;
        int lo = c, hi = NBIN - 1;
        while (lo < hi) {
            int mid = (lo + hi) >> 1;
            if (s_gbase[mid] > g) hi = mid; else lo = mid + 1;
        }
        unsigned idx = g - (s_gbase[lo] - s_hist[lo]);
        u.s.keys[i] = __ldcg(&g_seg[(size_t)(b * NBIN + lo) * SEGCAP + idx]);
    }
    __syncthreads();

    // rank by counting (keys unique)
    for (unsigned i = tid; i < n; i += 256) {
        unsigned long long key = u.s.keys[i];
        unsigned rank = 0;
        for (unsigned j = 0; j < n; j++) rank += (u.s.keys[j] > key);
        if (rank < K_TOP) {
            unsigned bits = (unsigned)(key >> 32);
            unsigned idx  = ~((unsigned)key);
            int yv = (int)(idx / W);
            int xv = (int)(idx - (unsigned)yv * W);
            u.s.score[rank] = __uint_as_float(bits);
            u.s.y[rank] = yv;
            u.s.x[rank] = xv;
            u.s.valid[rank] = 1;
        }
    }
    __syncthreads();

    // coors / scores / mask
    if (tid < K_TOP) {
        int v = u.s.valid[tid];
        int bk = b * K_TOP + tid;
        out[OFF_COORS  + bk * 2 + 0] = (float)u.s.y[tid];
        out[OFF_COORS  + bk * 2 + 1] = (float)u.s.x[tid];
        out[OFF_SCORES + bk]         = v ? u.s.score[tid] : 0.0f;
        out[OFF_MASK   + bk]         = v ? 1.0f : 0.0f;
    }

    // params gather: 1600 float4 per batch, MLP-7
    const float4* pms4 = (const float4*)pms;
    float4*       out4 = (float4*)(out + OFF_PARAMS);
    float4 vals[7];
    #pragma unroll
    for (int uu = 0; uu < 7; uu++) {
        int e = tid + uu * 256;
        vals[uu] = make_float4(0.f, 0.f, 0.f, 0.f);
        if (e < K_TOP * (P / 4)) {
            int k  = e >> 4;
            int cc = e & 15;
            if (u.s.valid[k]) {
                long long rowOff = ((long long)(b * H + u.s.y[k]) * W + u.s.x[k]) * (P / 4);
                vals[uu] = pms4[rowOff + cc];
            }
        }
    }
    #pragma unroll
    for (int uu = 0; uu < 7; uu++) {
        int e = tid + uu * 256;
        if (e < K_TOP * (P / 4)) {
            int k  = e >> 4;
            int cc = e & 15;
            out4[(long long)(b * K_TOP + k) * (P / 4) + cc] = vals[uu];
        }
    }
}

// ---------------------------------------------------------------------------
extern "C" void kernel_launch(void* const* d_in, const int* in_sizes, int n_in,
                              void* d_out, int out_size) {
    const float* hms = (const float*)d_in[0];
    const float* pms = (const float*)d_in[1];
    float* out = (float*)d_out;

    dim3 g(NBLK, B);
    k_fused<<<g, 256>>>(hms, pms, out);
}

// round 11
// speedup vs baseline: 1.1101x; 1.1101x over previous
#include <cuda_runtime.h>
#include <cuda_bf16.h>
#include <float.h>
#include <stdint.h>

#define B        16
#define H        320
#define W        320
#define HW       (H * W)
#define P        64
#define K_TOP    100
#define NBIN     256         // bins over (0.5, 1.0) by float-bit mantissa
#define SEGCAP   512         // per-(batch,bin) segment capacity
#define KEYCAP   1024        // K2 smem key cap (> K_TOP + SEGCAP)
#define LBUF     1024        // K1 per-block candidate cap
#define TR       10          // rows per K1 block (H % TR == 0)
#define NBLK     (H / TR)    // 32 blocks per batch

// Output layout (float32, tuple order): coors | params | scores | mask
#define OFF_COORS  0
#define OFF_PARAMS 3200
#define OFF_SCORES 105600
#define OFF_MASK   107200

// Device scratch (zero-init at module load; K2 resets counts -> replay safe)
__device__ unsigned           g_binc[B * NBIN];
__device__ unsigned long long g_seg[(size_t)B * NBIN * SEGCAP];

static __device__ __forceinline__ float fmax3(float a, float b, float c) {
    return fmaxf(fmaxf(a, b), c);
}
// bin 0..255 over score bits in [0x3F000000, 0x3F800000)
static __device__ __forceinline__ unsigned binOf(unsigned bits) {
    unsigned bn = (bits - 0x3F000000u) >> 15;
    return bn > (NBIN - 1u) ? (NBIN - 1u) : bn;
}
static __device__ __forceinline__ unsigned smem_u32(const void* p) {
    return (unsigned)__cvta_generic_to_shared(p);
}

// ---------------------------------------------------------------------------
// K1: TMA-bulk tile load, 3x3 peak NMS, scatter into per-(batch,bin) segments.
// Grid (NBLK, B), 256 threads.
// ---------------------------------------------------------------------------
__global__ __launch_bounds__(256) void k1_peaks(const float* __restrict__ hms) {
    __shared__ float s_tile[(TR + 2) * W];        // 15360 B
    __shared__ float s_cmax[TR * W];              // 12800 B
    __shared__ unsigned long long s_buf[LBUF];    // 8192 B
    __shared__ unsigned s_hist[NBIN];
    __shared__ unsigned s_gbase[NBIN];
    __shared__ unsigned s_loc[NBIN];
    __shared__ unsigned s_cnt;
    __shared__ __align__(8) unsigned long long s_mbar;

    const int b    = blockIdx.y;
    const int y0   = blockIdx.x * TR;
    const int tid  = threadIdx.x;
    const int lane = tid & 31;
    const float* hb = hms + b * HW;

    if (tid == 0) s_cnt = 0;
    s_hist[tid] = 0u;                             // NBIN == blockDim

    // ---- Bulk async copy of the contiguous row range [r0, r1] ----
    const int r0     = (y0 == 0) ? 0 : y0 - 1;
    const int r1     = (y0 + TR >= H) ? H - 1 : y0 + TR;
    const int nrows  = r1 - r0 + 1;               // 11 or 12
    const int dstRow = r0 - (y0 - 1);             // 0 or 1
    const unsigned bytes = (unsigned)(nrows * W * 4);
    const unsigned mbar  = smem_u32(&s_mbar);

    if (tid == 0)
        asm volatile("mbarrier.init.shared.b64 [%0], %1;" :: "r"(mbar), "r"(1u) : "memory");
    __syncthreads();
    if (tid == 0) {
        asm volatile("mbarrier.arrive.expect_tx.shared.b64 _, [%0], %1;"
                     :: "r"(mbar), "r"(bytes) : "memory");
        unsigned dst = smem_u32(&s_tile[dstRow * W]);
        const float* src = hb + r0 * W;
        asm volatile("cp.async.bulk.shared::cluster.global.mbarrier::complete_tx::bytes "
                     "[%0], [%1], %2, [%3];"
                     :: "r"(dst), "l"(src), "r"(bytes), "r"(mbar) : "memory");
    }

    // ---- Fill missing halo rows with -inf (outside the TMA region) ----
    if (y0 == 0) {
        for (int i = tid; i < W; i += 256) s_tile[i] = -FLT_MAX;
    }
    if (y0 + TR >= H) {
        for (int i = tid; i < W; i += 256) s_tile[(TR + 1) * W + i] = -FLT_MAX;
    }

    // ---- Wait for TMA completion ----
    {
        unsigned done;
        asm volatile(
            "{\n\t.reg .pred p;\n\t"
            "mbarrier.try_wait.parity.shared.b64 p, [%1], %2;\n\t"
            "selp.b32 %0, 1, 0, p;\n\t}"
            : "=r"(done) : "r"(mbar), "r"(0u) : "memory");
        while (!done) {
            asm volatile(
                "{\n\t.reg .pred p;\n\t"
                "mbarrier.try_wait.parity.shared.b64 p, [%1], %2;\n\t"
                "selp.b32 %0, 1, 0, p;\n\t}"
                : "=r"(done) : "r"(mbar), "r"(0u) : "memory");
        }
    }
    __syncthreads();

    // ---- Phase A: vertical 3-max (float4 in smem) ----
    #pragma unroll
    for (int uu = 0; uu < 4; uu++) {
        int i = tid + uu * 256;
        if (i < TR * (W / 4)) {
            int r  = i / (W / 4);
            int c4 = i - r * (W / 4);
            float4 a = ((const float4*)s_tile)[(r    ) * (W / 4) + c4];
            float4 m = ((const float4*)s_tile)[(r + 1) * (W / 4) + c4];
            float4 d = ((const float4*)s_tile)[(r + 2) * (W / 4) + c4];
            float4 o;
            o.x = fmax3(a.x, m.x, d.x);
            o.y = fmax3(a.y, m.y, d.y);
            o.z = fmax3(a.z, m.z, d.z);
            o.w = fmax3(a.w, m.w, d.w);
            ((float4*)s_cmax)[i] = o;
        }
    }
    __syncthreads();

    // ---- Phase B: horizontal 3-max + peak test + warp-aggregated compaction
    // (TR*W/4 = 800 work items = 25 full warps per pass: guards warp-uniform)
    #pragma unroll
    for (int uu = 0; uu < 4; uu++) {
        int i = tid + uu * 256;
        if (i < TR * (W / 4)) {
            int r  = i / (W / 4);
            int c4 = i - r * (W / 4);
            int x0 = c4 * 4;
            float4 mid = ((const float4*)s_tile)[(r + 1) * (W / 4) + c4];
            float4 cm  = ((const float4*)s_cmax)[r * (W / 4) + c4];
            float lf = (c4 > 0)         ? s_cmax[r * W + x0 - 1] : cm.x;
            float rt = (c4 < W / 4 - 1) ? s_cmax[r * W + x0 + 4] : cm.w;

            float wm[4];
            wm[0] = fmax3(lf,   cm.x, cm.y);
            wm[1] = fmax3(cm.x, cm.y, cm.z);
            wm[2] = fmax3(cm.y, cm.z, cm.w);
            wm[3] = fmax3(cm.z, cm.w, rt);
            float mv[4] = {mid.x, mid.y, mid.z, mid.w};

            #pragma unroll
            for (int e = 0; e < 4; e++) {
                bool cand = (mv[e] > 0.5f) && (mv[e] >= wm[e]);
                unsigned bal = __ballot_sync(0xffffffffu, cand);
                if (bal) {
                    unsigned base = 0;
                    if (lane == 0) base = atomicAdd(&s_cnt, (unsigned)__popc(bal));
                    base = __shfl_sync(0xffffffffu, base, 0);
                    if (cand) {
                        unsigned pos = base + (unsigned)__popc(bal & ((1u << lane) - 1u));
                        if (pos < LBUF) {
                            unsigned bits = __float_as_uint(mv[e]);
                            atomicAdd(&s_hist[binOf(bits)], 1u);
                            unsigned pixIdx = (unsigned)((y0 + r) * W + x0 + e);
                            s_buf[pos] = ((unsigned long long)bits << 32)
                                       | (unsigned)(~pixIdx);
                        }
                    }
                }
            }
        }
    }
    __syncthreads();

    // ---- Reserve per-bin global ranges (one atomic per non-empty bin) ----
    {
        unsigned h = s_hist[tid];
        s_gbase[tid] = h ? atomicAdd(&g_binc[b * NBIN + tid], h) : 0u;
        s_loc[tid] = 0u;
    }
    __syncthreads();

    // ---- Scatter keys into bin segments ----
    unsigned nb = s_cnt;
    if (nb > LBUF) nb = LBUF;
    for (unsigned i = tid; i < nb; i += 256) {
        unsigned long long key = s_buf[i];
        unsigned bin  = binOf((unsigned)(key >> 32));
        unsigned slot = s_gbase[bin] + atomicAdd(&s_loc[bin], 1u);
        if (slot < SEGCAP)
            g_seg[(size_t)(b * NBIN + bin) * SEGCAP + slot] = key;
    }
}

// ---------------------------------------------------------------------------
// K2: per batch — warp-scan cutoff, load only top bins, rank-count, outputs,
// gather, scratch reset. Grid B, 256 threads.
// ---------------------------------------------------------------------------
__global__ __launch_bounds__(256) void k2_select(const float* __restrict__ pms,
                                                 float* __restrict__ out) {
    __shared__ unsigned s_h[NBIN];        // bin counts
    __shared__ unsigned s_pre[NBIN];      // inclusive prefix
    __shared__ unsigned s_wsum[8];
    __shared__ int s_c;
    __shared__ unsigned long long s_keys[KEYCAP];
    __shared__ float s_score[K_TOP];
    __shared__ int   s_y[K_TOP], s_x[K_TOP], s_valid[K_TOP];

    const int b    = blockIdx.x;
    const int tid  = threadIdx.x;
    const int lane = tid & 31;
    const int wid  = tid >> 5;

    unsigned h;
    {
        unsigned v = g_binc[b * NBIN + tid];
        g_binc[b * NBIN + tid] = 0u;                // reset for next replay
        h = v > SEGCAP ? (unsigned)SEGCAP : v;
        s_h[tid] = h;
    }
    if (tid < K_TOP) { s_valid[tid] = 0; s_y[tid] = 0; s_x[tid] = 0; s_score[tid] = 0.f; }
    if (tid == 0) s_c = 0;
    __syncthreads();

    // ---- Inclusive prefix scan over 256 bins (warp shuffles) ----
    unsigned x = h;
    #pragma unroll
    for (int d = 1; d < 32; d <<= 1) {
        unsigned t = __shfl_up_sync(0xffffffffu, x, d);
        if (lane >= d) x += t;
    }
    if (lane == 31) s_wsum[wid] = x;
    __syncthreads();
    if (tid < 8) {
        unsigned y = s_wsum[tid];
        #pragma unroll
        for (int d = 1; d < 8; d <<= 1) {
            unsigned t = __shfl_up_sync(0xffu, y, d);
            if (tid >= d) y += t;
        }
        s_wsum[tid] = y;
    }
    __syncthreads();
    const unsigned Pinc = x + (wid ? s_wsum[wid - 1] : 0u);
    s_pre[tid] = Pinc;
    __syncthreads();

    const unsigned T = s_pre[NBIN - 1];
    if (T - Pinc + h >= K_TOP) atomicMax(&s_c, tid);    // keys in bins >= tid
    __syncthreads();
    const int c = s_c;
    const unsigned Pc = s_pre[c] - s_h[c];              // keys in bins < c
    unsigned n = T - Pc;
    if (n > KEYCAP) n = KEYCAP;

    // ---- Load only keys from bins >= c (binary search over prefix) ----
    for (unsigned i = tid; i < n; i += 256) {
        unsigned g = i + Pc;
        int lo = c, hi = NBIN - 1;
        while (lo < hi) {
            int mid = (lo + hi) >> 1;
            if (s_pre[mid] > g) hi = mid; else lo = mid + 1;
        }
        unsigned idx = g - (s_pre[lo] - s_h[lo]);
        s_keys[i] = g_seg[(size_t)(b * NBIN + lo) * SEGCAP + idx];
    }
    __syncthreads();

    // ---- Rank by counting (keys unique); fill top-K slots ----
    for (unsigned i = tid; i < n; i += 256) {
        unsigned long long key = s_keys[i];
        unsigned rank = 0;
        for (unsigned j = 0; j < n; j++) rank += (s_keys[j] > key);
        if (rank < K_TOP) {
            unsigned bits = (unsigned)(key >> 32);
            unsigned idx  = ~((unsigned)key);
            int yv = (int)(idx / W);
            int xv = (int)(idx - (unsigned)yv * W);
            s_score[rank] = __uint_as_float(bits);
            s_y[rank] = yv;
            s_x[rank] = xv;
            s_valid[rank] = 1;
        }
    }
    __syncthreads();

    // ---- coors / scores / mask ----
    if (tid < K_TOP) {
        int v = s_valid[tid];
        int bk = b * K_TOP + tid;
        out[OFF_COORS  + bk * 2 + 0] = (float)s_y[tid];
        out[OFF_COORS  + bk * 2 + 1] = (float)s_x[tid];
        out[OFF_SCORES + bk]         = v ? s_score[tid] : 0.0f;
        out[OFF_MASK   + bk]         = v ? 1.0f : 0.0f;
    }

    // ---- Params gather: 1600 float4 per batch, MLP-7 ----
    const float4* pms4 = (const float4*)pms;
    float4*       out4 = (float4*)(out + OFF_PARAMS);
    float4 vals[7];
    #pragma unroll
    for (int uu = 0; uu < 7; uu++) {
        int e = tid + uu * 256;
        vals[uu] = make_float4(0.f, 0.f, 0.f, 0.f);
        if (e < K_TOP * (P / 4)) {
            int k  = e >> 4;
            int cc = e & 15;
            if (s_valid[k]) {
                long long rowOff = ((long long)(b * H + s_y[k]) * W + s_x[k]) * (P / 4);
                vals[uu] = pms4[rowOff + cc];
            }
        }
    }
    #pragma unroll
    for (int uu = 0; uu < 7; uu++) {
        int e = tid + uu * 256;
        if (e < K_TOP * (P / 4)) {
            int k  = e >> 4;
            int cc = e & 15;
            out4[(long long)(b * K_TOP + k) * (P / 4) + cc] = vals[uu];
        }
    }
}

// ---------------------------------------------------------------------------
extern "C" void kernel_launch(void* const* d_in, const int* in_sizes, int n_in,
                              void* d_out, int out_size) {
    const float* hms = (const float*)d_in[0];
    const float* pms = (const float*)d_in[1];
    float* out = (float*)d_out;

    dim3 g1(NBLK, B);
    k1_peaks<<<g1, 256>>>(hms);
    k2_select<<<B, 256>>>(pms, out);
}

// round 12
// speedup vs baseline: 1.1269x; 1.0152x over previous
#include <cuda_runtime.h>
#include <cuda_bf16.h>
#include <float.h>
#include <stdint.h>

#define B        16
#define H        320
#define W        320
#define HW       (H * W)
#define P        64
#define K_TOP    100
#define NBIN     256         // bins over (0.5, 1.0) by float-bit mantissa
#define SEGCAP   512         // per-(batch,bin) segment capacity
#define KEYCAP   1024        // K2 smem key cap (> K_TOP + SEGCAP)
#define LBUF     1024        // K1 per-block candidate cap
#define TR       10          // rows per K1 block (H % TR == 0)
#define NBLK     (H / TR)    // 32 blocks per batch

// Output layout (float32, tuple order): coors | params | scores | mask
#define OFF_COORS  0
#define OFF_PARAMS 3200
#define OFF_SCORES 105600
#define OFF_MASK   107200

// Device scratch (zero-init at module load; K2 resets counts -> replay safe)
__device__ unsigned           g_binc[B * NBIN];
__device__ unsigned long long g_seg[(size_t)B * NBIN * SEGCAP];

static __device__ __forceinline__ float fmax3(float a, float b, float c) {
    return fmaxf(fmaxf(a, b), c);
}
// bin 0..255 over score bits in [0x3F000000, 0x3F800000)
static __device__ __forceinline__ unsigned binOf(unsigned bits) {
    unsigned bn = (bits - 0x3F000000u) >> 15;
    return bn > (NBIN - 1u) ? (NBIN - 1u) : bn;
}

// ---------------------------------------------------------------------------
// K1: float4-LDG tile load, 3x3 peak NMS, scatter into (batch,bin) segments.
// Grid (NBLK, B), 256 threads.
// ---------------------------------------------------------------------------
__global__ __launch_bounds__(256) void k1_peaks(const float* __restrict__ hms) {
    __shared__ float s_tile[(TR + 2) * W];        // 15360 B
    __shared__ float s_cmax[TR * W];              // 12800 B
    __shared__ unsigned long long s_buf[LBUF];    // 8192 B
    __shared__ unsigned s_hist[NBIN];
    __shared__ unsigned s_gbase[NBIN];
    __shared__ unsigned s_loc[NBIN];
    __shared__ unsigned s_cnt;

    const int b    = blockIdx.y;
    const int y0   = blockIdx.x * TR;
    const int tid  = threadIdx.x;
    const int lane = tid & 31;
    const float* hb = hms + b * HW;

    if (tid == 0) s_cnt = 0;
    s_hist[tid] = 0u;                             // NBIN == blockDim

    // ---- Load (TR+2) rows as float4; OOB rows = -inf ----
    #pragma unroll
    for (int uu = 0; uu < 4; uu++) {
        int i = tid + uu * 256;
        if (i < (TR + 2) * (W / 4)) {
            int r  = i / (W / 4);
            int gy = y0 - 1 + r;
            float4 v = make_float4(-FLT_MAX, -FLT_MAX, -FLT_MAX, -FLT_MAX);
            if (gy >= 0 && gy < H)
                v = ((const float4*)(hb + gy * W))[i - r * (W / 4)];
            ((float4*)s_tile)[i] = v;
        }
    }
    __syncthreads();

    // ---- Phase A: vertical 3-max (float4) ----
    #pragma unroll
    for (int uu = 0; uu < 4; uu++) {
        int i = tid + uu * 256;
        if (i < TR * (W / 4)) {
            int r  = i / (W / 4);
            int c4 = i - r * (W / 4);
            float4 a = ((const float4*)s_tile)[(r    ) * (W / 4) + c4];
            float4 m = ((const float4*)s_tile)[(r + 1) * (W / 4) + c4];
            float4 d = ((const float4*)s_tile)[(r + 2) * (W / 4) + c4];
            float4 o;
            o.x = fmax3(a.x, m.x, d.x);
            o.y = fmax3(a.y, m.y, d.y);
            o.z = fmax3(a.z, m.z, d.z);
            o.w = fmax3(a.w, m.w, d.w);
            ((float4*)s_cmax)[i] = o;
        }
    }
    __syncthreads();

    // ---- Phase B: horizontal 3-max + peak test + warp-aggregated compaction
    // (TR*W/4 = 800 work items = 25 full warps per pass: guards warp-uniform)
    #pragma unroll
    for (int uu = 0; uu < 4; uu++) {
        int i = tid + uu * 256;
        if (i < TR * (W / 4)) {
            int r  = i / (W / 4);
            int c4 = i - r * (W / 4);
            int x0 = c4 * 4;
            float4 mid = ((const float4*)s_tile)[(r + 1) * (W / 4) + c4];
            float4 cm  = ((const float4*)s_cmax)[r * (W / 4) + c4];
            float lf = (c4 > 0)         ? s_cmax[r * W + x0 - 1] : cm.x;
            float rt = (c4 < W / 4 - 1) ? s_cmax[r * W + x0 + 4] : cm.w;

            float wm[4];
            wm[0] = fmax3(lf,   cm.x, cm.y);
            wm[1] = fmax3(cm.x, cm.y, cm.z);
            wm[2] = fmax3(cm.y, cm.z, cm.w);
            wm[3] = fmax3(cm.z, cm.w, rt);
            float mv[4] = {mid.x, mid.y, mid.z, mid.w};

            #pragma unroll
            for (int e = 0; e < 4; e++) {
                bool cand = (mv[e] > 0.5f) && (mv[e] >= wm[e]);
                unsigned bal = __ballot_sync(0xffffffffu, cand);
                if (bal) {
                    unsigned base = 0;
                    if (lane == 0) base = atomicAdd(&s_cnt, (unsigned)__popc(bal));
                    base = __shfl_sync(0xffffffffu, base, 0);
                    if (cand) {
                        unsigned pos = base + (unsigned)__popc(bal & ((1u << lane) - 1u));
                        if (pos < LBUF) {
                            unsigned bits = __float_as_uint(mv[e]);
                            atomicAdd(&s_hist[binOf(bits)], 1u);
                            unsigned pixIdx = (unsigned)((y0 + r) * W + x0 + e);
                            s_buf[pos] = ((unsigned long long)bits << 32)
                                       | (unsigned)(~pixIdx);
                        }
                    }
                }
            }
        }
    }
    __syncthreads();

    // ---- Reserve per-bin global ranges (one atomic per non-empty bin) ----
    {
        unsigned h = s_hist[tid];
        s_gbase[tid] = h ? atomicAdd(&g_binc[b * NBIN + tid], h) : 0u;
        s_loc[tid] = 0u;
    }
    __syncthreads();

    // ---- Scatter keys into bin segments ----
    unsigned nb = s_cnt;
    if (nb > LBUF) nb = LBUF;
    for (unsigned i = tid; i < nb; i += 256) {
        unsigned long long key = s_buf[i];
        unsigned bin  = binOf((unsigned)(key >> 32));
        unsigned slot = s_gbase[bin] + atomicAdd(&s_loc[bin], 1u);
        if (slot < SEGCAP)
            g_seg[(size_t)(b * NBIN + bin) * SEGCAP + slot] = key;
    }
}

// ---------------------------------------------------------------------------
// K2: per batch — warp-scan cutoff, load only top bins, rank-count, outputs,
// gather, scratch reset. Grid B, 256 threads. PDL-synchronized against K1.
// ---------------------------------------------------------------------------
__global__ __launch_bounds__(256) void k2_select(const float* __restrict__ pms,
                                                 float* __restrict__ out) {
    __shared__ unsigned s_h[NBIN];
    __shared__ unsigned s_pre[NBIN];
    __shared__ unsigned s_wsum[8];
    __shared__ int s_c;
    __shared__ unsigned long long s_keys[KEYCAP];
    __shared__ float s_score[K_TOP];
    __shared__ int   s_y[K_TOP], s_x[K_TOP], s_valid[K_TOP];

    const int b    = blockIdx.x;
    const int tid  = threadIdx.x;
    const int lane = tid & 31;
    const int wid  = tid >> 5;

    // Prologue that needs no K1 data
    if (tid < K_TOP) { s_valid[tid] = 0; s_y[tid] = 0; s_x[tid] = 0; s_score[tid] = 0.f; }
    if (tid == 0) s_c = 0;

    // Wait for K1 grid completion (PDL); no-op under a plain launch
    cudaGridDependencySynchronize();

    unsigned h;
    {
        unsigned v = g_binc[b * NBIN + tid];
        g_binc[b * NBIN + tid] = 0u;                // reset for next replay
        h = v > SEGCAP ? (unsigned)SEGCAP : v;
        s_h[tid] = h;
    }
    __syncthreads();

    // ---- Inclusive prefix scan over 256 bins (warp shuffles) ----
    unsigned x = h;
    #pragma unroll
    for (int d = 1; d < 32; d <<= 1) {
        unsigned t = __shfl_up_sync(0xffffffffu, x, d);
        if (lane >= d) x += t;
    }
    if (lane == 31) s_wsum[wid] = x;
    __syncthreads();
    if (tid < 8) {
        unsigned y = s_wsum[tid];
        #pragma unroll
        for (int d = 1; d < 8; d <<= 1) {
            unsigned t = __shfl_up_sync(0xffu, y, d);
            if (tid >= d) y += t;
        }
        s_wsum[tid] = y;
    }
    __syncthreads();
    const unsigned Pinc = x + (wid ? s_wsum[wid - 1] : 0u);
    s_pre[tid] = Pinc;
    __syncthreads();

    const unsigned T = s_pre[NBIN - 1];
    if (T - Pinc + h >= K_TOP) atomicMax(&s_c, tid);    // keys in bins >= tid
    __syncthreads();
    const int c = s_c;
    const unsigned Pc = s_pre[c] - s_h[c];              // keys in bins < c
    unsigned n = T - Pc;
    if (n > KEYCAP) n = KEYCAP;

    // ---- Load only keys from bins >= c (binary search over prefix) ----
    for (unsigned i = tid; i < n; i += 256) {
        unsigned g = i + Pc;
        int lo = c, hi = NBIN - 1;
        while (lo < hi) {
            int mid = (lo + hi) >> 1;
            if (s_pre[mid] > g) hi = mid; else lo = mid + 1;
        }
        unsigned idx = g - (s_pre[lo] - s_h[lo]);
        s_keys[i] = g_seg[(size_t)(b * NBIN + lo) * SEGCAP + idx];
    }
    __syncthreads();

    // ---- Rank by counting (keys unique); fill top-K slots ----
    for (unsigned i = tid; i < n; i += 256) {
        unsigned long long key = s_keys[i];
        unsigned rank = 0;
        for (unsigned j = 0; j < n; j++) rank += (s_keys[j] > key);
        if (rank < K_TOP) {
            unsigned bits = (unsigned)(key >> 32);
            unsigned idx  = ~((unsigned)key);
            int yv = (int)(idx / W);
            int xv = (int)(idx - (unsigned)yv * W);
            s_score[rank] = __uint_as_float(bits);
            s_y[rank] = yv;
            s_x[rank] = xv;
            s_valid[rank] = 1;
        }
    }
    __syncthreads();

    // ---- coors / scores / mask ----
    if (tid < K_TOP) {
        int v = s_valid[tid];
        int bk = b * K_TOP + tid;
        out[OFF_COORS  + bk * 2 + 0] = (float)s_y[tid];
        out[OFF_COORS  + bk * 2 + 1] = (float)s_x[tid];
        out[OFF_SCORES + bk]         = v ? s_score[tid] : 0.0f;
        out[OFF_MASK   + bk]         = v ? 1.0f : 0.0f;
    }

    // ---- Params gather: 1600 float4 per batch, MLP-7 ----
    const float4* pms4 = (const float4*)pms;
    float4*       out4 = (float4*)(out + OFF_PARAMS);
    float4 vals[7];
    #pragma unroll
    for (int uu = 0; uu < 7; uu++) {
        int e = tid + uu * 256;
        vals[uu] = make_float4(0.f, 0.f, 0.f, 0.f);
        if (e < K_TOP * (P / 4)) {
            int k  = e >> 4;
            int cc = e & 15;
            if (s_valid[k]) {
                long long rowOff = ((long long)(b * H + s_y[k]) * W + s_x[k]) * (P / 4);
                vals[uu] = pms4[rowOff + cc];
            }
        }
    }
    #pragma unroll
    for (int uu = 0; uu < 7; uu++) {
        int e = tid + uu * 256;
        if (e < K_TOP * (P / 4)) {
            int k  = e >> 4;
            int cc = e & 15;
            out4[(long long)(b * K_TOP + k) * (P / 4) + cc] = vals[uu];
        }
    }
}

// ---------------------------------------------------------------------------
extern "C" void kernel_launch(void* const* d_in, const int* in_sizes, int n_in,
                              void* d_out, int out_size) {
    const float* hms = (const float*)d_in[0];
    const float* pms = (const float*)d_in[1];
    float* out = (float*)d_out;

    dim3 g1(NBLK, B);
    k1_peaks<<<g1, 256>>>(hms);

    // K2 with a programmatic (PDL) dependency on K1; fall back to a plain
    // launch if the attribute/Ex-launch is rejected.
    cudaLaunchConfig_t cfg = {};
    cfg.gridDim  = dim3(B);
    cfg.blockDim = dim3(256);
    cfg.dynamicSmemBytes = 0;
    cfg.stream = 0;
    cudaLaunchAttribute attr[1];
    attr[0].id = cudaLaunchAttributeProgrammaticStreamSerialization;
    attr[0].val.programmaticStreamSerializationAllowed = 1;
    cfg.attrs = attr;
    cfg.numAttrs = 1;
    cudaError_t e = cudaLaunchKernelEx(&cfg, k2_select, pms, out);
    if (e != cudaSuccess) {
        k2_select<<<B, 256>>>(pms, out);
    }
}